// round 6
// baseline (speedup 1.0000x reference)
#include <cuda_runtime.h>
#include <cuda_bf16.h>
#include <cstdint>

// ---------------- problem constants ----------------
#define TSEQ 2048
#define EDIM 1024
#define HD   32          // q/k head dim
#define DV   64          // v head dim (2*hd)
#define NQH  32          // 2*H attention heads for q/k
#define NH   16          // H value heads
#define LAMBDA_INIT_C 0.47071301834358415f   // 0.8 - 0.6*exp(-0.6)

// ---------------- scratch (device globals; no allocation allowed) ----------
__device__ float g_Q[TSEQ * EDIM];
__device__ float g_K[TSEQ * EDIM];
__device__ float g_V[TSEQ * EDIM];
__device__ float g_Ohead[NQH * TSEQ * DV];   // per-attention-head flash output
__device__ float g_attn[TSEQ * EDIM];        // normalized concat, pre-Wo
__device__ float g_lambda;

// ============================================================================
// SGEMM (NT): C[M,N] = A[M,K] * B[N,K]^T, all row-major fp32.
// 128x128 block tile, BK=16, 8x8 per thread, 256 threads.
// ============================================================================
#define BM 128
#define BN 128
#define BK 16
__global__ __launch_bounds__(256)
void sgemm_nt(const float* __restrict__ A, const float* __restrict__ B,
              float* __restrict__ C, int M, int N, int K)
{
    __shared__ float As[BK][BM + 4];
    __shared__ float Bs[BK][BN + 4];

    const int tid = threadIdx.x;
    const int tx  = tid & 15;
    const int ty  = tid >> 4;
    const int bm  = blockIdx.y * BM;
    const int bn  = blockIdx.x * BN;

    const int lr = tid >> 2;          // 0..63
    const int lc = (tid & 3) << 2;    // 0,4,8,12

    float acc[8][8];
#pragma unroll
    for (int i = 0; i < 8; ++i)
#pragma unroll
        for (int j = 0; j < 8; ++j) acc[i][j] = 0.f;

    for (int k0 = 0; k0 < K; k0 += BK) {
#pragma unroll
        for (int r = 0; r < 2; ++r) {
            const int row = lr + r * 64;
            float4 va = *(const float4*)(A + (size_t)(bm + row) * K + k0 + lc);
            As[lc + 0][row] = va.x; As[lc + 1][row] = va.y;
            As[lc + 2][row] = va.z; As[lc + 3][row] = va.w;
            float4 vb = *(const float4*)(B + (size_t)(bn + row) * K + k0 + lc);
            Bs[lc + 0][row] = vb.x; Bs[lc + 1][row] = vb.y;
            Bs[lc + 2][row] = vb.z; Bs[lc + 3][row] = vb.w;
        }
        __syncthreads();

#pragma unroll
        for (int kk = 0; kk < BK; ++kk) {
            float a[8], b[8];
#pragma unroll
            for (int i = 0; i < 8; ++i) a[i] = As[kk][ty * 8 + i];
#pragma unroll
            for (int j = 0; j < 8; ++j) b[j] = Bs[kk][tx * 8 + j];
#pragma unroll
            for (int i = 0; i < 8; ++i)
#pragma unroll
                for (int j = 0; j < 8; ++j)
                    acc[i][j] += a[i] * b[j];
        }
        __syncthreads();
    }

#pragma unroll
    for (int i = 0; i < 8; ++i) {
        const int row = bm + ty * 8 + i;
#pragma unroll
        for (int j = 0; j < 8; j += 4) {
            float4 v = make_float4(acc[i][j], acc[i][j + 1], acc[i][j + 2], acc[i][j + 3]);
            *(float4*)(C + (size_t)row * N + bn + tx * 8 + j) = v;
        }
    }
}

// ============================================================================
// lambda scalar: exp(sum(lq1*lk1)) - exp(sum(lq2*lk2)) + lambda_init
// ============================================================================
__global__ void lambda_kernel(const float* __restrict__ lq1, const float* __restrict__ lk1,
                              const float* __restrict__ lq2, const float* __restrict__ lk2)
{
    const int lane = threadIdx.x;
    float a = lq1[lane] * lk1[lane];
    float b = lq2[lane] * lk2[lane];
#pragma unroll
    for (int off = 16; off; off >>= 1) {
        a += __shfl_xor_sync(0xffffffffu, a, off);
        b += __shfl_xor_sync(0xffffffffu, b, off);
    }
    if (lane == 0) g_lambda = __expf(a) - __expf(b) + LAMBDA_INIT_C;
}

// ============================================================================
// Flash attention (causal, fp32), per attention head (32 heads, hd=32, dv=64).
// Block: 256 threads (16x16). Q tile = 64 rows, KV tile = 32 rows.
// Each thread: 4 S-rows x 2 S-cols, 4 O-rows x 4 O-cols.
// ============================================================================
#define FBM 64
#define FBN 32
__global__ __launch_bounds__(256)
void diff_flash_kernel(const float* __restrict__ Q, const float* __restrict__ K,
                       const float* __restrict__ V, float* __restrict__ O)
{
    __shared__ float qs[FBM][HD + 1];
    __shared__ float ks[FBN][HD + 1];
    __shared__ float vs[FBN][DV + 1];
    __shared__ float ps[FBM][FBN + 1];

    const int h   = blockIdx.y;          // 0..31
    const int it  = blockIdx.x;          // q tile index
    const int tid = threadIdx.x;
    const int tx  = tid & 15;
    const int ty  = tid >> 4;
    const int qbase = it * FBM;
    const int qoff  = h * HD;            // column offset in Q/K rows (stride EDIM)
    const int voff  = (h >> 1) * DV;     // column offset in V rows

    // load Q tile (64 x 32)
#pragma unroll
    for (int r = 0; r < 8; ++r) {
        const int row = r * 8 + (tid >> 5);
        const int col = tid & 31;
        qs[row][col] = Q[(size_t)(qbase + row) * EDIM + qoff + col];
    }

    float m[4], l[4], acc[4][4];
#pragma unroll
    for (int i = 0; i < 4; ++i) {
        m[i] = -1e30f; l[i] = 0.f;
#pragma unroll
        for (int j = 0; j < 4; ++j) acc[i][j] = 0.f;
    }
    const float scale = 0.17677669529663689f;   // 1/sqrt(32)

    const int njt = 2 * it + 2;
    for (int jt = 0; jt < njt; ++jt) {
        __syncthreads();   // protect ks/vs/ps from previous iteration's readers
        {
            const int row = tid >> 5;    // 0..7
            const int col = tid & 31;
#pragma unroll
            for (int r = 0; r < 4; ++r)
                ks[row + r * 8][col] =
                    K[(size_t)(jt * FBN + row + r * 8) * EDIM + qoff + col];
#pragma unroll
            for (int r = 0; r < 8; ++r) {
                const int idx = r * 256 + tid;
                const int vr = idx >> 6, vc = idx & 63;
                vs[vr][vc] = V[(size_t)(jt * FBN + vr) * EDIM + voff + vc];
            }
        }
        __syncthreads();

        // S = q k^T for my 4x2 micro-tile
        float s[4][2];
#pragma unroll
        for (int i = 0; i < 4; ++i) { s[i][0] = 0.f; s[i][1] = 0.f; }
#pragma unroll
        for (int k = 0; k < HD; ++k) {
            const float b0 = ks[tx * 2 + 0][k];
            const float b1 = ks[tx * 2 + 1][k];
#pragma unroll
            for (int i = 0; i < 4; ++i) {
                const float a = qs[ty * 4 + i][k];
                s[i][0] += a * b0;
                s[i][1] += a * b1;
            }
        }

        // scale + causal mask, online softmax
#pragma unroll
        for (int i = 0; i < 4; ++i) {
            const int grow = qbase + ty * 4 + i;
#pragma unroll
            for (int j = 0; j < 2; ++j) {
                const int gcol = jt * FBN + tx * 2 + j;
                s[i][j] = (gcol <= grow) ? s[i][j] * scale : -1e30f;
            }
            float tm = fmaxf(s[i][0], s[i][1]);
#pragma unroll
            for (int off = 8; off; off >>= 1)
                tm = fmaxf(tm, __shfl_xor_sync(0xffffffffu, tm, off));
            const float mn   = fmaxf(m[i], tm);
            const float corr = __expf(m[i] - mn);
            const float p0 = __expf(s[i][0] - mn);
            const float p1 = __expf(s[i][1] - mn);
            float rs = p0 + p1;
#pragma unroll
            for (int off = 8; off; off >>= 1)
                rs += __shfl_xor_sync(0xffffffffu, rs, off);
            l[i] = l[i] * corr + rs;
            m[i] = mn;
            ps[ty * 4 + i][tx * 2 + 0] = p0;
            ps[ty * 4 + i][tx * 2 + 1] = p1;
#pragma unroll
            for (int j = 0; j < 4; ++j) acc[i][j] *= corr;
        }
        __syncthreads();

        // O += P @ V
#pragma unroll
        for (int kk = 0; kk < FBN; ++kk) {
            float pv[4], vv[4];
#pragma unroll
            for (int i = 0; i < 4; ++i) pv[i] = ps[ty * 4 + i][kk];
#pragma unroll
            for (int j = 0; j < 4; ++j) vv[j] = vs[kk][tx * 4 + j];
#pragma unroll
            for (int i = 0; i < 4; ++i)
#pragma unroll
                for (int j = 0; j < 4; ++j)
                    acc[i][j] += pv[i] * vv[j];
        }
    }

    // epilogue: O /= l, store [head][t][64]
#pragma unroll
    for (int i = 0; i < 4; ++i) {
        const float inv = 1.f / l[i];
        const int row = qbase + ty * 4 + i;
        float4 o = make_float4(acc[i][0] * inv, acc[i][1] * inv,
                               acc[i][2] * inv, acc[i][3] * inv);
        *(float4*)(O + ((size_t)h * TSEQ + row) * DV + tx * 4) = o;
    }
}

// ============================================================================
// Combine: out1 - lambda*out2, RMSNorm(64), gamma, *(1-lambda_init)
// One warp per (token, value-head) group; lane handles dims lane, lane+32.
// ============================================================================
__global__ __launch_bounds__(256)
void combine_kernel(const float* __restrict__ O, const float* __restrict__ gamma,
                    float* __restrict__ out)
{
    const int tid  = threadIdx.x;
    const int warp = tid >> 5;
    const int lane = tid & 31;
    const int g = blockIdx.x * 8 + warp;     // 0 .. TSEQ*NH-1
    const int t = g >> 4;
    const int h = g & 15;

    const float lam = g_lambda;
    const float w   = 1.0f - LAMBDA_INIT_C;

    const size_t b1 = ((size_t)(2 * h) * TSEQ + t) * DV;
    const size_t b2 = ((size_t)(2 * h + 1) * TSEQ + t) * DV;
    const float o0 = O[b1 + lane]      - lam * O[b2 + lane];
    const float o1 = O[b1 + lane + 32] - lam * O[b2 + lane + 32];

    float ss = o0 * o0 + o1 * o1;
#pragma unroll
    for (int off = 16; off; off >>= 1)
        ss += __shfl_xor_sync(0xffffffffu, ss, off);
    const float r = rsqrtf(ss * (1.f / 64.f) + 1e-5f);

    out[(size_t)t * EDIM + h * DV + lane]      = gamma[lane]      * o0 * r * w;
    out[(size_t)t * EDIM + h * DV + lane + 32] = gamma[lane + 32] * o1 * r * w;
}

// ============================================================================
// launch
// ============================================================================
extern "C" void kernel_launch(void* const* d_in, const int* in_sizes, int n_in,
                              void* d_out, int out_size)
{
    const float* x   = (const float*)d_in[0];
    const float* Wq  = (const float*)d_in[1];
    const float* Wk  = (const float*)d_in[2];
    const float* Wv  = (const float*)d_in[3];
    const float* Wo  = (const float*)d_in[4];
    const float* lq1 = (const float*)d_in[5];
    const float* lk1 = (const float*)d_in[6];
    const float* lq2 = (const float*)d_in[7];
    const float* lk2 = (const float*)d_in[8];
    const float* gam = (const float*)d_in[9];
    float* out = (float*)d_out;

    float *pQ, *pK, *pV, *pO, *pA;
    cudaGetSymbolAddress((void**)&pQ, g_Q);
    cudaGetSymbolAddress((void**)&pK, g_K);
    cudaGetSymbolAddress((void**)&pV, g_V);
    cudaGetSymbolAddress((void**)&pO, g_Ohead);
    cudaGetSymbolAddress((void**)&pA, g_attn);

    dim3 gemm_grid(EDIM / BN, TSEQ / BM);
    sgemm_nt<<<gemm_grid, 256>>>(x, Wq, pQ, TSEQ, EDIM, EDIM);
    sgemm_nt<<<gemm_grid, 256>>>(x, Wk, pK, TSEQ, EDIM, EDIM);
    sgemm_nt<<<gemm_grid, 256>>>(x, Wv, pV, TSEQ, EDIM, EDIM);

    lambda_kernel<<<1, 32>>>(lq1, lk1, lq2, lk2);

    dim3 fa_grid(TSEQ / FBM, NQH);
    diff_flash_kernel<<<fa_grid, 256>>>(pQ, pK, pV, pO);

    combine_kernel<<<(TSEQ * NH) / 8, 256>>>(pO, gam, pA);

    sgemm_nt<<<gemm_grid, 256>>>(pA, Wo, out, TSEQ, EDIM, EDIM);
}

// round 7
// speedup vs baseline: 1.0023x; 1.0023x over previous
#include <cuda_runtime.h>
#include <cuda_bf16.h>
#include <cstdint>

// ---------------- problem constants ----------------
#define TSEQ 2048
#define EDIM 1024
#define HD   32          // q/k head dim
#define DV   64          // v head dim (2*hd)
#define NQH  32          // 2*H attention heads for q/k
#define NH   16          // H value heads
#define LAMBDA_INIT_C 0.47071301834358415f   // 0.8 - 0.6*exp(-0.6)

// ---------------- scratch (device globals; no allocation allowed) ----------
__device__ float g_Q[TSEQ * EDIM];
__device__ float g_K[TSEQ * EDIM];
__device__ float g_V[TSEQ * EDIM];
__device__ float g_Ohead[NQH * TSEQ * DV];   // per-attention-head flash output
__device__ float g_attn[TSEQ * EDIM];        // normalized concat, pre-Wo
__device__ float g_lambda;

// ============================================================================
// SGEMM (NT): C[M,N] = A[M,K] * B[N,K]^T, all row-major fp32.
// 128x128 block tile, BK=16, 8x8 per thread, 256 threads.
// ============================================================================
#define BM 128
#define BN 128
#define BK 16
__global__ __launch_bounds__(256)
void sgemm_nt(const float* __restrict__ A, const float* __restrict__ B,
              float* __restrict__ C, int M, int N, int K)
{
    __shared__ float As[BK][BM + 4];
    __shared__ float Bs[BK][BN + 4];

    const int tid = threadIdx.x;
    const int tx  = tid & 15;
    const int ty  = tid >> 4;
    const int bm  = blockIdx.y * BM;
    const int bn  = blockIdx.x * BN;

    const int lr = tid >> 2;          // 0..63
    const int lc = (tid & 3) << 2;    // 0,4,8,12

    float acc[8][8];
#pragma unroll
    for (int i = 0; i < 8; ++i)
#pragma unroll
        for (int j = 0; j < 8; ++j) acc[i][j] = 0.f;

    for (int k0 = 0; k0 < K; k0 += BK) {
#pragma unroll
        for (int r = 0; r < 2; ++r) {
            const int row = lr + r * 64;
            float4 va = *(const float4*)(A + (size_t)(bm + row) * K + k0 + lc);
            As[lc + 0][row] = va.x; As[lc + 1][row] = va.y;
            As[lc + 2][row] = va.z; As[lc + 3][row] = va.w;
            float4 vb = *(const float4*)(B + (size_t)(bn + row) * K + k0 + lc);
            Bs[lc + 0][row] = vb.x; Bs[lc + 1][row] = vb.y;
            Bs[lc + 2][row] = vb.z; Bs[lc + 3][row] = vb.w;
        }
        __syncthreads();

#pragma unroll
        for (int kk = 0; kk < BK; ++kk) {
            float a[8], b[8];
#pragma unroll
            for (int i = 0; i < 8; ++i) a[i] = As[kk][ty * 8 + i];
#pragma unroll
            for (int j = 0; j < 8; ++j) b[j] = Bs[kk][tx * 8 + j];
#pragma unroll
            for (int i = 0; i < 8; ++i)
#pragma unroll
                for (int j = 0; j < 8; ++j)
                    acc[i][j] += a[i] * b[j];
        }
        __syncthreads();
    }

#pragma unroll
    for (int i = 0; i < 8; ++i) {
        const int row = bm + ty * 8 + i;
#pragma unroll
        for (int j = 0; j < 8; j += 4) {
            float4 v = make_float4(acc[i][j], acc[i][j + 1], acc[i][j + 2], acc[i][j + 3]);
            *(float4*)(C + (size_t)row * N + bn + tx * 8 + j) = v;
        }
    }
}

// ============================================================================
// lambda scalar: exp(sum(lq1*lk1)) - exp(sum(lq2*lk2)) + lambda_init
// ============================================================================
__global__ void lambda_kernel(const float* __restrict__ lq1, const float* __restrict__ lk1,
                              const float* __restrict__ lq2, const float* __restrict__ lk2)
{
    const int lane = threadIdx.x;
    float a = lq1[lane] * lk1[lane];
    float b = lq2[lane] * lk2[lane];
#pragma unroll
    for (int off = 16; off; off >>= 1) {
        a += __shfl_xor_sync(0xffffffffu, a, off);
        b += __shfl_xor_sync(0xffffffffu, b, off);
    }
    if (lane == 0) g_lambda = __expf(a) - __expf(b) + LAMBDA_INIT_C;
}

// ============================================================================
// Flash attention (causal, fp32), per attention head (32 heads, hd=32, dv=64).
// Block: 256 threads (16x16). Q tile = 64 rows, KV tile = 32 rows.
// Each thread: 4 S-rows x 2 S-cols, 4 O-rows x 4 O-cols.
// ============================================================================
#define FBM 64
#define FBN 32
__global__ __launch_bounds__(256)
void diff_flash_kernel(const float* __restrict__ Q, const float* __restrict__ K,
                       const float* __restrict__ V, float* __restrict__ O)
{
    __shared__ float qs[FBM][HD + 1];
    __shared__ float ks[FBN][HD + 1];
    __shared__ float vs[FBN][DV + 1];
    __shared__ float ps[FBM][FBN + 1];

    const int h   = blockIdx.y;          // 0..31
    const int it  = blockIdx.x;          // q tile index
    const int tid = threadIdx.x;
    const int tx  = tid & 15;
    const int ty  = tid >> 4;
    const int qbase = it * FBM;
    const int qoff  = h * HD;            // column offset in Q/K rows (stride EDIM)
    const int voff  = (h >> 1) * DV;     // column offset in V rows

    // load Q tile (64 x 32)
#pragma unroll
    for (int r = 0; r < 8; ++r) {
        const int row = r * 8 + (tid >> 5);
        const int col = tid & 31;
        qs[row][col] = Q[(size_t)(qbase + row) * EDIM + qoff + col];
    }

    float m[4], l[4], acc[4][4];
#pragma unroll
    for (int i = 0; i < 4; ++i) {
        m[i] = -1e30f; l[i] = 0.f;
#pragma unroll
        for (int j = 0; j < 4; ++j) acc[i][j] = 0.f;
    }
    const float scale = 0.17677669529663689f;   // 1/sqrt(32)

    const int njt = 2 * it + 2;
    for (int jt = 0; jt < njt; ++jt) {
        __syncthreads();   // protect ks/vs/ps from previous iteration's readers
        {
            const int row = tid >> 5;    // 0..7
            const int col = tid & 31;
#pragma unroll
            for (int r = 0; r < 4; ++r)
                ks[row + r * 8][col] =
                    K[(size_t)(jt * FBN + row + r * 8) * EDIM + qoff + col];
#pragma unroll
            for (int r = 0; r < 8; ++r) {
                const int idx = r * 256 + tid;
                const int vr = idx >> 6, vc = idx & 63;
                vs[vr][vc] = V[(size_t)(jt * FBN + vr) * EDIM + voff + vc];
            }
        }
        __syncthreads();

        // S = q k^T for my 4x2 micro-tile
        float s[4][2];
#pragma unroll
        for (int i = 0; i < 4; ++i) { s[i][0] = 0.f; s[i][1] = 0.f; }
#pragma unroll
        for (int k = 0; k < HD; ++k) {
            const float b0 = ks[tx * 2 + 0][k];
            const float b1 = ks[tx * 2 + 1][k];
#pragma unroll
            for (int i = 0; i < 4; ++i) {
                const float a = qs[ty * 4 + i][k];
                s[i][0] += a * b0;
                s[i][1] += a * b1;
            }
        }

        // scale + causal mask, online softmax
#pragma unroll
        for (int i = 0; i < 4; ++i) {
            const int grow = qbase + ty * 4 + i;
#pragma unroll
            for (int j = 0; j < 2; ++j) {
                const int gcol = jt * FBN + tx * 2 + j;
                s[i][j] = (gcol <= grow) ? s[i][j] * scale : -1e30f;
            }
            float tm = fmaxf(s[i][0], s[i][1]);
#pragma unroll
            for (int off = 8; off; off >>= 1)
                tm = fmaxf(tm, __shfl_xor_sync(0xffffffffu, tm, off));
            const float mn   = fmaxf(m[i], tm);
            const float corr = __expf(m[i] - mn);
            const float p0 = __expf(s[i][0] - mn);
            const float p1 = __expf(s[i][1] - mn);
            float rs = p0 + p1;
#pragma unroll
            for (int off = 8; off; off >>= 1)
                rs += __shfl_xor_sync(0xffffffffu, rs, off);
            l[i] = l[i] * corr + rs;
            m[i] = mn;
            ps[ty * 4 + i][tx * 2 + 0] = p0;
            ps[ty * 4 + i][tx * 2 + 1] = p1;
#pragma unroll
            for (int j = 0; j < 4; ++j) acc[i][j] *= corr;
        }
        __syncthreads();

        // O += P @ V
#pragma unroll
        for (int kk = 0; kk < FBN; ++kk) {
            float pv[4], vv[4];
#pragma unroll
            for (int i = 0; i < 4; ++i) pv[i] = ps[ty * 4 + i][kk];
#pragma unroll
            for (int j = 0; j < 4; ++j) vv[j] = vs[kk][tx * 4 + j];
#pragma unroll
            for (int i = 0; i < 4; ++i)
#pragma unroll
                for (int j = 0; j < 4; ++j)
                    acc[i][j] += pv[i] * vv[j];
        }
    }

    // epilogue: O /= l, store [head][t][64]
#pragma unroll
    for (int i = 0; i < 4; ++i) {
        const float inv = 1.f / l[i];
        const int row = qbase + ty * 4 + i;
        float4 o = make_float4(acc[i][0] * inv, acc[i][1] * inv,
                               acc[i][2] * inv, acc[i][3] * inv);
        *(float4*)(O + ((size_t)h * TSEQ + row) * DV + tx * 4) = o;
    }
}

// ============================================================================
// Combine: out1 - lambda*out2, RMSNorm(64), gamma, *(1-lambda_init)
// One warp per (token, value-head) group; lane handles dims lane, lane+32.
// ============================================================================
__global__ __launch_bounds__(256)
void combine_kernel(const float* __restrict__ O, const float* __restrict__ gamma,
                    float* __restrict__ out)
{
    const int tid  = threadIdx.x;
    const int warp = tid >> 5;
    const int lane = tid & 31;
    const int g = blockIdx.x * 8 + warp;     // 0 .. TSEQ*NH-1
    const int t = g >> 4;
    const int h = g & 15;

    const float lam = g_lambda;
    const float w   = 1.0f - LAMBDA_INIT_C;

    const size_t b1 = ((size_t)(2 * h) * TSEQ + t) * DV;
    const size_t b2 = ((size_t)(2 * h + 1) * TSEQ + t) * DV;
    const float o0 = O[b1 + lane]      - lam * O[b2 + lane];
    const float o1 = O[b1 + lane + 32] - lam * O[b2 + lane + 32];

    float ss = o0 * o0 + o1 * o1;
#pragma unroll
    for (int off = 16; off; off >>= 1)
        ss += __shfl_xor_sync(0xffffffffu, ss, off);
    const float r = rsqrtf(ss * (1.f / 64.f) + 1e-5f);

    out[(size_t)t * EDIM + h * DV + lane]      = gamma[lane]      * o0 * r * w;
    out[(size_t)t * EDIM + h * DV + lane + 32] = gamma[lane + 32] * o1 * r * w;
}

// ============================================================================
// launch
// ============================================================================
extern "C" void kernel_launch(void* const* d_in, const int* in_sizes, int n_in,
                              void* d_out, int out_size)
{
    const float* x   = (const float*)d_in[0];
    const float* Wq  = (const float*)d_in[1];
    const float* Wk  = (const float*)d_in[2];
    const float* Wv  = (const float*)d_in[3];
    const float* Wo  = (const float*)d_in[4];
    const float* lq1 = (const float*)d_in[5];
    const float* lk1 = (const float*)d_in[6];
    const float* lq2 = (const float*)d_in[7];
    const float* lk2 = (const float*)d_in[8];
    const float* gam = (const float*)d_in[9];
    float* out = (float*)d_out;

    float *pQ, *pK, *pV, *pO, *pA;
    cudaGetSymbolAddress((void**)&pQ, g_Q);
    cudaGetSymbolAddress((void**)&pK, g_K);
    cudaGetSymbolAddress((void**)&pV, g_V);
    cudaGetSymbolAddress((void**)&pO, g_Ohead);
    cudaGetSymbolAddress((void**)&pA, g_attn);

    dim3 gemm_grid(EDIM / BN, TSEQ / BM);
    sgemm_nt<<<gemm_grid, 256>>>(x, Wq, pQ, TSEQ, EDIM, EDIM);
    sgemm_nt<<<gemm_grid, 256>>>(x, Wk, pK, TSEQ, EDIM, EDIM);
    sgemm_nt<<<gemm_grid, 256>>>(x, Wv, pV, TSEQ, EDIM, EDIM);

    lambda_kernel<<<1, 32>>>(lq1, lk1, lq2, lk2);

    dim3 fa_grid(TSEQ / FBM, NQH);
    diff_flash_kernel<<<fa_grid, 256>>>(pQ, pK, pV, pO);

    combine_kernel<<<(TSEQ * NH) / 8, 256>>>(pO, gam, pA);

    sgemm_nt<<<gemm_grid, 256>>>(pA, Wo, out, TSEQ, EDIM, EDIM);
}

// round 10
// speedup vs baseline: 1.3453x; 1.3422x over previous
#include <cuda_runtime.h>
#include <cuda_bf16.h>
#include <cstdint>

#define TSEQ 2048
#define EDIM 1024
#define HD   32
#define DV   64
#define NQH  32
#define NH   16
#define LAMBDA_INIT_C 0.47071301834358415f

__device__ float g_Q[TSEQ * EDIM];
__device__ float g_K[TSEQ * EDIM];
__device__ float g_V[TSEQ * EDIM];
__device__ float g_Ohead[NQH * TSEQ * DV];
__device__ float g_attn[TSEQ * EDIM];
__device__ float g_lambda;
__device__ __nv_bfloat16 g_xh[TSEQ * EDIM],  g_xl[TSEQ * EDIM];
__device__ __nv_bfloat16 g_wqh[EDIM * EDIM], g_wql[EDIM * EDIM];
__device__ __nv_bfloat16 g_wkh[EDIM * EDIM], g_wkl[EDIM * EDIM];
__device__ __nv_bfloat16 g_wvh[EDIM * EDIM], g_wvl[EDIM * EDIM];
__device__ __nv_bfloat16 g_woh[EDIM * EDIM], g_wol[EDIM * EDIM];
__device__ __nv_bfloat16 g_ah[TSEQ * EDIM],  g_al[TSEQ * EDIM];

__device__ __forceinline__ uint32_t smem_u32(const void* p) {
    uint32_t a;
    asm("{ .reg .u64 t; cvta.to.shared.u64 t, %1; cvt.u32.u64 %0, t; }" : "=r"(a) : "l"(p));
    return a;
}
__device__ __forceinline__ void ldm_x4(uint32_t* r, uint32_t addr) {
    asm volatile("ldmatrix.sync.aligned.m8n8.x4.shared.b16 {%0,%1,%2,%3}, [%4];"
                 : "=r"(r[0]), "=r"(r[1]), "=r"(r[2]), "=r"(r[3]) : "r"(addr));
}
__device__ __forceinline__ void hmma(float* d, const uint32_t* a, const uint32_t* b) {
    asm volatile("mma.sync.aligned.m16n8k16.row.col.f32.bf16.bf16.f32 "
                 "{%0,%1,%2,%3}, {%4,%5,%6,%7}, {%8,%9}, {%0,%1,%2,%3};"
                 : "+f"(d[0]), "+f"(d[1]), "+f"(d[2]), "+f"(d[3])
                 : "r"(a[0]), "r"(a[1]), "r"(a[2]), "r"(a[3]), "r"(b[0]), "r"(b[1]));
}
#define CP_ASYNC16(s, g) asm volatile("cp.async.cg.shared.global [%0], [%1], 16;" :: "r"(s), "l"(g))
#define CP_COMMIT()      asm volatile("cp.async.commit_group;" ::: "memory")
#define CP_WAIT1()       asm volatile("cp.async.wait_group 1;" ::: "memory")

// ---------------- fp32 -> (hi, lo) bf16 split ----------------
__global__ __launch_bounds__(256)
void split_kernel(const float* __restrict__ x, __nv_bfloat16* __restrict__ hi,
                  __nv_bfloat16* __restrict__ lo)
{
    int i = (blockIdx.x * 256 + threadIdx.x) * 4;
    float4 v = *(const float4*)(x + i);
    __nv_bfloat16 h0 = __float2bfloat16(v.x), h1 = __float2bfloat16(v.y);
    __nv_bfloat16 h2 = __float2bfloat16(v.z), h3 = __float2bfloat16(v.w);
    __nv_bfloat162* H = (__nv_bfloat162*)(hi + i);
    __nv_bfloat162* L = (__nv_bfloat162*)(lo + i);
    H[0] = __halves2bfloat162(h0, h1);
    H[1] = __halves2bfloat162(h2, h3);
    L[0] = __halves2bfloat162(__float2bfloat16(v.x - __bfloat162float(h0)),
                              __float2bfloat16(v.y - __bfloat162float(h1)));
    L[1] = __halves2bfloat162(__float2bfloat16(v.z - __bfloat162float(h2)),
                              __float2bfloat16(v.w - __bfloat162float(h3)));
}

// ============================================================================
// HMMA bf16x3 GEMM (NT): C[2048,1024] = A*B^T. CTA 128x128, BK=32, 3-stage
// cp.async pipeline. Smem rows padded to 80B (conflict-free ldmatrix).
// ============================================================================
#define GSTR   80                    // bytes per padded 32-bf16 row
#define GTILEB (128 * GSTR)          // 10240 bytes per tile
#define GSTAGE (4 * GTILEB)          // Ah, Al, Bh, Bl
#define GSMEM  (3 * GSTAGE)          // 122880

__global__ __launch_bounds__(256)
void gemm_hmma(const __nv_bfloat16* __restrict__ Ah, const __nv_bfloat16* __restrict__ Al,
               const __nv_bfloat16* __restrict__ Bh, const __nv_bfloat16* __restrict__ Bl,
               float* __restrict__ C)
{
    extern __shared__ char sm[];
    const uint32_t sb = smem_u32(sm);
    const int tid  = threadIdx.x;
    const int lane = tid & 31;
    const int wid  = tid >> 5;
    const int wm   = wid >> 2;          // 0..1
    const int wn   = wid & 3;           // 0..3
    const int bm   = blockIdx.y * 128;
    const int bn   = blockIdx.x * 128;

    // ---- cp.async mapping: 4 tiles x (128 rows x 64B); 64 threads/tile, 8 segs/thread
    const int lt = tid >> 6;            // which tile
    const int u  = tid & 63;
    const int lrow0 = u >> 2;           // + i*16
    const int lcseg = (u & 3) * 16;     // byte offset within row
    const char* gsrc;
    {
        const char* s0 = (const char*)(Ah + (size_t)bm * EDIM);
        const char* s1 = (const char*)(Al + (size_t)bm * EDIM);
        const char* s2 = (const char*)(Bh + (size_t)bn * EDIM);
        const char* s3 = (const char*)(Bl + (size_t)bn * EDIM);
        gsrc = (lt == 0) ? s0 : (lt == 1) ? s1 : (lt == 2) ? s2 : s3;
    }
    const uint32_t sdst0 = sb + lt * GTILEB + lrow0 * GSTR + lcseg;

    auto issue = [&](int c, int st) {
        const char* g = gsrc + (size_t)lrow0 * 2048 + (size_t)c * 64 + lcseg;
        uint32_t s = sdst0 + st * GSTAGE;
#pragma unroll
        for (int i = 0; i < 8; ++i)
            CP_ASYNC16(s + i * 16 * GSTR, g + (size_t)i * 16 * 2048);
        CP_COMMIT();
    };

    // ---- ldmatrix per-thread offsets (bytes within a tile)
    const uint32_t offA = (uint32_t)((wm * 64 + (lane & 15)) * GSTR + ((lane >> 4) * 8) * 2);
    const uint32_t offB = (uint32_t)((wn * 32 + (lane & 7) + (lane >> 4) * 8) * GSTR
                                     + (((lane >> 3) & 1) * 8) * 2);

    float acc[4][4][4];
#pragma unroll
    for (int i = 0; i < 4; ++i)
#pragma unroll
        for (int j = 0; j < 4; ++j)
#pragma unroll
            for (int k = 0; k < 4; ++k) acc[i][j][k] = 0.f;

    issue(0, 0);
    issue(1, 1);

    for (int c = 0; c < 32; ++c) {
        CP_WAIT1();
        __syncthreads();
        if (c + 2 < 32) issue(c + 2, (c + 2) % 3);

        const uint32_t stb = sb + (c % 3) * GSTAGE;
        const uint32_t tAh = stb, tAl = stb + GTILEB;
        const uint32_t tBh = stb + 2 * GTILEB, tBl = stb + 3 * GTILEB;

#pragma unroll
        for (int ks = 0; ks < 2; ++ks) {
            const uint32_t ko = ks * 32;   // 16 bf16 = 32 bytes
            uint32_t ah[4][4], al[4][4], bh[2][4], bl[2][4];
#pragma unroll
            for (int mf = 0; mf < 4; ++mf) {
                ldm_x4(ah[mf], tAh + offA + mf * (16 * GSTR) + ko);
                ldm_x4(al[mf], tAl + offA + mf * (16 * GSTR) + ko);
            }
#pragma unroll
            for (int nf = 0; nf < 2; ++nf) {
                ldm_x4(bh[nf], tBh + offB + nf * (16 * GSTR) + ko);
                ldm_x4(bl[nf], tBl + offB + nf * (16 * GSTR) + ko);
            }
#pragma unroll
            for (int mf = 0; mf < 4; ++mf)
#pragma unroll
                for (int nf = 0; nf < 4; ++nf) {
                    const uint32_t* BH = &bh[nf >> 1][(nf & 1) * 2];
                    const uint32_t* BL = &bl[nf >> 1][(nf & 1) * 2];
                    hmma(acc[mf][nf], ah[mf], BH);
                    hmma(acc[mf][nf], ah[mf], BL);
                    hmma(acc[mf][nf], al[mf], BH);
                }
        }
        __syncthreads();
    }

    // epilogue
    const int mrow = bm + wm * 64 + (lane >> 2);
    const int ncol = bn + wn * 32 + (lane & 3) * 2;
#pragma unroll
    for (int mf = 0; mf < 4; ++mf)
#pragma unroll
        for (int nf = 0; nf < 4; ++nf) {
            float* p0 = C + (size_t)(mrow + mf * 16) * EDIM + ncol + nf * 8;
            float* p1 = p0 + 8 * EDIM;
            *(float2*)p0 = make_float2(acc[mf][nf][0], acc[mf][nf][1]);
            *(float2*)p1 = make_float2(acc[mf][nf][2], acc[mf][nf][3]);
        }
}

// ---------------- lambda ----------------
__global__ void lambda_kernel(const float* __restrict__ lq1, const float* __restrict__ lk1,
                              const float* __restrict__ lq2, const float* __restrict__ lk2)
{
    const int lane = threadIdx.x;
    float a = lq1[lane] * lk1[lane];
    float b = lq2[lane] * lk2[lane];
#pragma unroll
    for (int off = 16; off; off >>= 1) {
        a += __shfl_xor_sync(0xffffffffu, a, off);
        b += __shfl_xor_sync(0xffffffffu, b, off);
    }
    if (lane == 0) g_lambda = __expf(a) - __expf(b) + LAMBDA_INIT_C;
}

// ============================================================================
// Flash attention v2 (causal fp32): Q tile 64, KV tile 64, 16x16 threads,
// 4x4 micro-tiles, transposed q/k smem -> float4 LDS in the S loop.
// ============================================================================
#define FBM 64
#define FBN 64
__global__ __launch_bounds__(256)
void diff_flash2(const float* __restrict__ Q, const float* __restrict__ K,
                 const float* __restrict__ V, float* __restrict__ O)
{
    __shared__ float qs[HD][FBM];
    __shared__ float ks[HD][FBN];
    __shared__ float vs[FBN][DV];
    __shared__ float ps[FBM][FBN];

    const int h = blockIdx.y, it = blockIdx.x, tid = threadIdx.x;
    const int tx = tid & 15, ty = tid >> 4;
    const int qbase = it * FBM, qoff = h * HD, voff = (h >> 1) * DV;

    {
        const int row = tid & 63;
        const int cb  = tid >> 6;
#pragma unroll
        for (int i = 0; i < 8; ++i) {
            const int col = cb + i * 4;
            qs[col][row] = Q[(size_t)(qbase + row) * EDIM + qoff + col];
        }
    }

    float m[4], l[4], acc[4][4];
#pragma unroll
    for (int i = 0; i < 4; ++i) {
        m[i] = -1e30f; l[i] = 0.f;
#pragma unroll
        for (int j = 0; j < 4; ++j) acc[i][j] = 0.f;
    }
    const float scale = 0.17677669529663689f;

    for (int jt = 0; jt <= it; ++jt) {
        __syncthreads();
        {
            const int row = tid & 63;
            const int cb  = tid >> 6;
#pragma unroll
            for (int i = 0; i < 8; ++i) {
                const int col = cb + i * 4;
                ks[col][row] = K[(size_t)(jt * FBN + row) * EDIM + qoff + col];
            }
            const int vr = tid >> 4;
            const int vc = (tid & 15) << 2;
#pragma unroll
            for (int i = 0; i < 4; ++i) {
                const int r2 = vr + i * 16;
                *(float4*)&vs[r2][vc] =
                    *(const float4*)(V + (size_t)(jt * FBN + r2) * EDIM + voff + vc);
            }
        }
        __syncthreads();

        float s[4][4];
#pragma unroll
        for (int i = 0; i < 4; ++i)
#pragma unroll
            for (int j = 0; j < 4; ++j) s[i][j] = 0.f;
#pragma unroll
        for (int k = 0; k < HD; ++k) {
            const float4 a4 = *(const float4*)&qs[k][ty << 2];
            const float4 b4 = *(const float4*)&ks[k][tx << 2];
            const float av[4] = {a4.x, a4.y, a4.z, a4.w};
            const float bv[4] = {b4.x, b4.y, b4.z, b4.w};
#pragma unroll
            for (int i = 0; i < 4; ++i)
#pragma unroll
                for (int j = 0; j < 4; ++j) s[i][j] += av[i] * bv[j];
        }

#pragma unroll
        for (int i = 0; i < 4; ++i) {
            const int grow = qbase + (ty << 2) + i;
            const int cb2  = jt * FBN + (tx << 2);
#pragma unroll
            for (int j = 0; j < 4; ++j)
                s[i][j] = (cb2 + j <= grow) ? s[i][j] * scale : -1e30f;
            float tm = fmaxf(fmaxf(s[i][0], s[i][1]), fmaxf(s[i][2], s[i][3]));
#pragma unroll
            for (int off = 8; off; off >>= 1)
                tm = fmaxf(tm, __shfl_xor_sync(0xffffffffu, tm, off));
            const float mn   = fmaxf(m[i], tm);
            const float corr = __expf(m[i] - mn);
            float p[4], rs = 0.f;
#pragma unroll
            for (int j = 0; j < 4; ++j) { p[j] = __expf(s[i][j] - mn); rs += p[j]; }
#pragma unroll
            for (int off = 8; off; off >>= 1)
                rs += __shfl_xor_sync(0xffffffffu, rs, off);
            l[i] = l[i] * corr + rs;
            m[i] = mn;
            *(float4*)&ps[(ty << 2) + i][tx << 2] = make_float4(p[0], p[1], p[2], p[3]);
#pragma unroll
            for (int j = 0; j < 4; ++j) acc[i][j] *= corr;
        }
        __syncthreads();

#pragma unroll
        for (int kk = 0; kk < FBN; kk += 4) {
            float4 p4[4], v4[4];
#pragma unroll
            for (int i = 0; i < 4; ++i) p4[i] = *(const float4*)&ps[(ty << 2) + i][kk];
#pragma unroll
            for (int mm = 0; mm < 4; ++mm) v4[mm] = *(const float4*)&vs[kk + mm][tx << 2];
#pragma unroll
            for (int i = 0; i < 4; ++i) {
                const float pv[4] = {p4[i].x, p4[i].y, p4[i].z, p4[i].w};
#pragma unroll
                for (int mm = 0; mm < 4; ++mm) {
                    acc[i][0] += pv[mm] * v4[mm].x;
                    acc[i][1] += pv[mm] * v4[mm].y;
                    acc[i][2] += pv[mm] * v4[mm].z;
                    acc[i][3] += pv[mm] * v4[mm].w;
                }
            }
        }
    }

#pragma unroll
    for (int i = 0; i < 4; ++i) {
        const float inv = 1.f / l[i];
        const int row = qbase + (ty << 2) + i;
        *(float4*)(O + ((size_t)h * TSEQ + row) * DV + (tx << 2)) =
            make_float4(acc[i][0] * inv, acc[i][1] * inv, acc[i][2] * inv, acc[i][3] * inv);
    }
}

// ---------------- combine ----------------
__global__ __launch_bounds__(256)
void combine_kernel(const float* __restrict__ O, const float* __restrict__ gamma,
                    float* __restrict__ out)
{
    const int tid = threadIdx.x, warp = tid >> 5, lane = tid & 31;
    const int g = blockIdx.x * 8 + warp;
    const int t = g >> 4, h = g & 15;
    const float lam = g_lambda, w = 1.0f - LAMBDA_INIT_C;

    const size_t b1 = ((size_t)(2 * h) * TSEQ + t) * DV;
    const size_t b2 = ((size_t)(2 * h + 1) * TSEQ + t) * DV;
    const float o0 = O[b1 + lane]      - lam * O[b2 + lane];
    const float o1 = O[b1 + lane + 32] - lam * O[b2 + lane + 32];

    float ss = o0 * o0 + o1 * o1;
#pragma unroll
    for (int off = 16; off; off >>= 1)
        ss += __shfl_xor_sync(0xffffffffu, ss, off);
    const float r = rsqrtf(ss * (1.f / 64.f) + 1e-5f);

    out[(size_t)t * EDIM + h * DV + lane]      = gamma[lane]      * o0 * r * w;
    out[(size_t)t * EDIM + h * DV + lane + 32] = gamma[lane + 32] * o1 * r * w;
}

// ---------------- launch ----------------
extern "C" void kernel_launch(void* const* d_in, const int* in_sizes, int n_in,
                              void* d_out, int out_size)
{
    const float* x   = (const float*)d_in[0];
    const float* Wq  = (const float*)d_in[1];
    const float* Wk  = (const float*)d_in[2];
    const float* Wv  = (const float*)d_in[3];
    const float* Wo  = (const float*)d_in[4];
    const float* lq1 = (const float*)d_in[5];
    const float* lk1 = (const float*)d_in[6];
    const float* lq2 = (const float*)d_in[7];
    const float* lk2 = (const float*)d_in[8];
    const float* gam = (const float*)d_in[9];
    float* out = (float*)d_out;

    float *pQ, *pK, *pV, *pO, *pA;
    __nv_bfloat16 *xh, *xl, *wqh, *wql, *wkh, *wkl, *wvh, *wvl, *woh, *wol, *ah, *al;
    cudaGetSymbolAddress((void**)&pQ, g_Q);
    cudaGetSymbolAddress((void**)&pK, g_K);
    cudaGetSymbolAddress((void**)&pV, g_V);
    cudaGetSymbolAddress((void**)&pO, g_Ohead);
    cudaGetSymbolAddress((void**)&pA, g_attn);
    cudaGetSymbolAddress((void**)&xh, g_xh);   cudaGetSymbolAddress((void**)&xl, g_xl);
    cudaGetSymbolAddress((void**)&wqh, g_wqh); cudaGetSymbolAddress((void**)&wql, g_wql);
    cudaGetSymbolAddress((void**)&wkh, g_wkh); cudaGetSymbolAddress((void**)&wkl, g_wkl);
    cudaGetSymbolAddress((void**)&wvh, g_wvh); cudaGetSymbolAddress((void**)&wvl, g_wvl);
    cudaGetSymbolAddress((void**)&woh, g_woh); cudaGetSymbolAddress((void**)&wol, g_wol);
    cudaGetSymbolAddress((void**)&ah, g_ah);   cudaGetSymbolAddress((void**)&al, g_al);

    cudaFuncSetAttribute(gemm_hmma, cudaFuncAttributeMaxDynamicSharedMemorySize, GSMEM);

    const int nx = TSEQ * EDIM, nw = EDIM * EDIM;
    split_kernel<<<nx / 1024, 256>>>(x,  xh,  xl);
    split_kernel<<<nw / 1024, 256>>>(Wq, wqh, wql);
    split_kernel<<<nw / 1024, 256>>>(Wk, wkh, wkl);
    split_kernel<<<nw / 1024, 256>>>(Wv, wvh, wvl);
    split_kernel<<<nw / 1024, 256>>>(Wo, woh, wol);

    dim3 gg(EDIM / 128, TSEQ / 128);
    gemm_hmma<<<gg, 256, GSMEM>>>(xh, xl, wqh, wql, pQ);
    gemm_hmma<<<gg, 256, GSMEM>>>(xh, xl, wkh, wkl, pK);
    gemm_hmma<<<gg, 256, GSMEM>>>(xh, xl, wvh, wvl, pV);

    lambda_kernel<<<1, 32>>>(lq1, lk1, lq2, lk2);

    dim3 fg(TSEQ / FBM, NQH);
    diff_flash2<<<fg, 256>>>(pQ, pK, pV, pO);

    combine_kernel<<<(TSEQ * NH) / 8, 256>>>(pO, gam, pA);

    split_kernel<<<nx / 1024, 256>>>(pA, ah, al);
    gemm_hmma<<<gg, 256, GSMEM>>>(ah, al, woh, wol, out);
}